// round 3
// baseline (speedup 1.0000x reference)
#include <cuda_runtime.h>
#include <math.h>

#define N_NODES 40000
#define N_EDGES 640000
#define HID     128
#define NH      (N_NODES * HID)

// ---------------- device scratch (no allocations allowed) ----------------
__device__ __align__(16) float g_xproj[NH];
__device__ __align__(16) float g_state[NH];
__device__ __align__(16) float g_aggr[NH];
__device__ __align__(16) float g_wt[HID * HID];
__device__ int   g_rowptr[N_NODES + 1];
__device__ int   g_cursor[N_NODES];
__device__ int   g_counts[N_NODES];
__device__ int   g_col[N_EDGES];
__device__ int   g_is64;

// ---------------- edge dtype probe: int64 vs int32 ----------------
__global__ void detect_kernel(const void* ei) {
    if (threadIdx.x == 0 && blockIdx.x == 0) {
        const long long* p = (const long long*)ei;
        int ok64 = 1;
        for (int i = 0; i < 64; i++) {
            // indices < 640000: safe under both interpretations
            long long v = p[(i * 9973) % 640000];
            if (v < 0 || v >= N_NODES) { ok64 = 0; break; }
        }
        g_is64 = ok64;
    }
}

__device__ __forceinline__ int edge_val(const void* ei, int idx) {
    int v;
    if (g_is64) v = (int)((const long long*)ei)[idx];
    else        v = ((const int*)ei)[idx];
    return ((unsigned)v < N_NODES) ? v : 0;   // clamp: never trap
}

// ---------------- CSR build ----------------
__global__ void zero_counts_kernel() {
    for (int i = blockIdx.x * blockDim.x + threadIdx.x; i < N_NODES;
         i += gridDim.x * blockDim.x)
        g_counts[i] = 0;
}

__global__ void hist_kernel(const void* __restrict__ ei) {
    int e = blockIdx.x * blockDim.x + threadIdx.x;
    if (e < N_EDGES) {
        int dst = edge_val(ei, N_EDGES + e);
        atomicAdd(&g_counts[dst], 1);
    }
}

// single-block scan over counts -> rowptr (and cursor = exclusive prefix)
__global__ void scan_kernel() {
    __shared__ int sdata[1024];
    __shared__ int s_offset;
    int t = threadIdx.x;
    if (t == 0) { s_offset = 0; g_rowptr[0] = 0; }
    __syncthreads();
    for (int base = 0; base < N_NODES; base += 1024) {
        int i = base + t;
        int v = (i < N_NODES) ? g_counts[i] : 0;
        sdata[t] = v;
        __syncthreads();
        for (int off = 1; off < 1024; off <<= 1) {
            int x = (t >= off) ? sdata[t - off] : 0;
            __syncthreads();
            sdata[t] += x;
            __syncthreads();
        }
        int inc = sdata[t];
        if (i < N_NODES) {
            g_rowptr[i + 1] = s_offset + inc;
            g_cursor[i]     = s_offset + inc - v;
        }
        __syncthreads();
        if (t == 1023) s_offset += sdata[1023];
        __syncthreads();
    }
}

__global__ void fill_kernel(const void* __restrict__ ei) {
    int e = blockIdx.x * blockDim.x + threadIdx.x;
    if (e < N_EDGES) {
        int src = edge_val(ei, e);
        int dst = edge_val(ei, N_EDGES + e);
        int pos = atomicAdd(&g_cursor[dst], 1);
        if ((unsigned)pos < N_EDGES) g_col[pos] = src;
    }
}

// ---------------- edge aggregation: warp per node, float4 lanes ----------------
__global__ void __launch_bounds__(256) aggregate_kernel() {
    int node = blockIdx.x * 8 + (threadIdx.x >> 5);
    if (node >= N_NODES) return;
    int lane = threadIdx.x & 31;
    int s = g_rowptr[node];
    int e = g_rowptr[node + 1];
    const float4* st = (const float4*)g_state;
    float4 acc = make_float4(0.f, 0.f, 0.f, 0.f);
    for (int i = s; i < e; i++) {
        int src = g_col[i];
        float4 v = st[src * 32 + lane];
        acc.x += v.x; acc.y += v.y; acc.z += v.z; acc.w += v.w;
    }
    ((float4*)g_aggr)[node * 32 + lane] = acc;
}

// ---------------- transpose 128x128 into g_wt: wt[k][h] = w[h][k] ----------------
__global__ void transpose128_kernel(const float* __restrict__ w) {
    int idx = blockIdx.x * blockDim.x + threadIdx.x;
    if (idx < HID * HID) {
        int h = idx >> 7, k = idx & 127;
        g_wt[k * HID + h] = w[h * HID + k];
    }
}

// ---------------- first state update: state = tanh(xproj) ----------------
__global__ void tanh_kernel() {
    int i = blockIdx.x * blockDim.x + threadIdx.x;
    if (i < NH) g_state[i] = tanhf(g_xproj[i]);
}

// ---------------- fp32 GEMM: dst[n][h] = (tanh)((bias?) xproj + sum_k A[n][k]*W[k][h]) ----
// 64 rows per block, 256 threads, each thread 4 rows x 8 cols. K tiled by 32
// so static shared stays under the 48 KB default (no func attributes needed).
#define GR    64
#define KT    32
#define SAPAD (GR + 1)

// a_sel:   0 = Aext, 1 = g_state, 2 = g_aggr
// W:       Wext if non-null, else g_wt
// dst_sel: 0 = g_state, 1 = g_xproj, 2 = dst_ext
__global__ void __launch_bounds__(256) gemm_kernel(
    const float* __restrict__ Aext, int a_sel,
    const float* __restrict__ Wext,
    int use_bias, int dst_sel, float* __restrict__ dst_ext, int do_tanh)
{
    __shared__ float sW[KT * HID];     // [kk][h]
    __shared__ float sA[KT * SAPAD];   // [kk][r]

    const float* A = (a_sel == 0) ? Aext : ((a_sel == 1) ? g_state : g_aggr);
    const float* W = Wext ? Wext : g_wt;
    float* dst = (dst_sel == 0) ? g_state : ((dst_sel == 1) ? g_xproj : dst_ext);

    int t = threadIdx.x;
    int row0 = blockIdx.x * GR;
    int tc = t & 15;    // cols tc*8 .. +7
    int tr = t >> 4;    // rows tr*4 .. +3

    float acc[4][8];
#pragma unroll
    for (int i = 0; i < 4; i++)
#pragma unroll
        for (int j = 0; j < 8; j++) acc[i][j] = 0.f;

    for (int k0 = 0; k0 < HID; k0 += KT) {
        // load W tile: rows k0..k0+31 contiguous (4096 floats = 1024 float4)
        {
            const float4* Wv = (const float4*)(W + k0 * HID);
            float4* sWv = (float4*)sW;
#pragma unroll
            for (int j = 0; j < 4; j++) sWv[t + j * 256] = Wv[t + j * 256];
        }
        // load A tile transposed: 64 rows x 32 k = 512 float4
        {
#pragma unroll
            for (int j = 0; j < 2; j++) {
                int idx = t + j * 256;        // 0..511
                int r   = idx >> 3;           // 0..63
                int k4  = idx & 7;            // 0..7
                float4 v = *(const float4*)&A[(row0 + r) * HID + k0 + k4 * 4];
                sA[(k4 * 4 + 0) * SAPAD + r] = v.x;
                sA[(k4 * 4 + 1) * SAPAD + r] = v.y;
                sA[(k4 * 4 + 2) * SAPAD + r] = v.z;
                sA[(k4 * 4 + 3) * SAPAD + r] = v.w;
            }
        }
        __syncthreads();

#pragma unroll
        for (int kk = 0; kk < KT; kk++) {
            float4 w0 = *(const float4*)&sW[kk * HID + tc * 8];
            float4 w1 = *(const float4*)&sW[kk * HID + tc * 8 + 4];
            float a0 = sA[kk * SAPAD + tr * 4 + 0];
            float a1 = sA[kk * SAPAD + tr * 4 + 1];
            float a2 = sA[kk * SAPAD + tr * 4 + 2];
            float a3 = sA[kk * SAPAD + tr * 4 + 3];
            float wv[8] = {w0.x, w0.y, w0.z, w0.w, w1.x, w1.y, w1.z, w1.w};
            float av[4] = {a0, a1, a2, a3};
#pragma unroll
            for (int i = 0; i < 4; i++)
#pragma unroll
                for (int j = 0; j < 8; j++) acc[i][j] = fmaf(av[i], wv[j], acc[i][j]);
        }
        __syncthreads();
    }

#pragma unroll
    for (int i = 0; i < 4; i++) {
        int r = row0 + tr * 4 + i;
        float v[8];
#pragma unroll
        for (int j = 0; j < 8; j++) v[j] = acc[i][j];
        if (use_bias) {
            float4 b0 = *(const float4*)&g_xproj[r * HID + tc * 8];
            float4 b1 = *(const float4*)&g_xproj[r * HID + tc * 8 + 4];
            v[0] += b0.x; v[1] += b0.y; v[2] += b0.z; v[3] += b0.w;
            v[4] += b1.x; v[5] += b1.y; v[6] += b1.z; v[7] += b1.w;
        }
        if (do_tanh) {
#pragma unroll
            for (int j = 0; j < 8; j++) v[j] = tanhf(v[j]);
        }
        *(float4*)&dst[r * HID + tc * 8]     = make_float4(v[0], v[1], v[2], v[3]);
        *(float4*)&dst[r * HID + tc * 8 + 4] = make_float4(v[4], v[5], v[6], v[7]);
    }
}

// ---------------- host orchestration ----------------
extern "C" void kernel_launch(void* const* d_in, const int* in_sizes, int n_in,
                              void* d_out, int out_size)
{
    // Discover inputs by element count (robust to metadata ordering):
    //   edge_index: 1,280,000   x: 5,120,000   weights: 4 x 16,384 (in order)
    const void* ei = nullptr;
    const float* x = nullptr;
    const float* w[4] = {nullptr, nullptr, nullptr, nullptr};
    int wn = 0;
    for (int i = 0; i < n_in; i++) {
        if (in_sizes[i] == 2 * N_EDGES)      ei = d_in[i];
        else if (in_sizes[i] == NH)          x  = (const float*)d_in[i];
        else if (in_sizes[i] == HID * HID && wn < 4) w[wn++] = (const float*)d_in[i];
    }
    const float* w_in0  = w[0];
    const float* w_rec0 = w[1];
    const float* w_in1  = w[2];
    const float* w_rec1 = w[3];
    float* out = (float*)d_out;

    // Build dst-major CSR once per launch
    detect_kernel<<<1, 32>>>(ei);
    zero_counts_kernel<<<40, 1024>>>();
    hist_kernel<<<(N_EDGES + 255) / 256, 256>>>(ei);
    scan_kernel<<<1, 1024>>>();
    fill_kernel<<<(N_EDGES + 255) / 256, 256>>>(ei);

    const int GEMM_BLOCKS = N_NODES / GR;        // 625
    const int TANH_BLOCKS = (NH + 255) / 256;
    const int AGGR_BLOCKS = (N_NODES + 7) / 8;   // 5000 (8 warps/block)

    for (int layer = 0; layer < 2; layer++) {
        const float* win  = layer ? w_in1  : w_in0;
        const float* wrec = layer ? w_rec1 : w_rec0;

        // xproj = input @ win^T  (input: x for layer 0, g_state for layer 1)
        transpose128_kernel<<<64, 256>>>(win);
        gemm_kernel<<<GEMM_BLOCKS, 256>>>(
            layer ? nullptr : x, layer ? 1 : 0,   // A
            nullptr,                              // W = g_wt (transposed)
            0, /*dst=xproj*/ 1, nullptr, 0);

        // state update #1 (initial state zero): state = tanh(xproj)
        tanh_kernel<<<TANH_BLOCKS, 256>>>();

        // 8 more updates: state = tanh(xproj + aggr(state) @ wrec)
        for (int it = 0; it < 8; it++) {
            aggregate_kernel<<<AGGR_BLOCKS, 256>>>();
            int last = (layer == 1 && it == 7);
            gemm_kernel<<<GEMM_BLOCKS, 256>>>(
                nullptr, /*A=g_aggr*/ 2,
                wrec,
                /*bias*/ 1, last ? 2 : 0, last ? out : nullptr, /*tanh*/ 1);
        }
    }
}